// round 9
// baseline (speedup 1.0000x reference)
#include <cuda_runtime.h>
#include <cuda_fp16.h>

#define N_NODES 100000
#define N_EDGES 1600000
#define D_HID   64
#define D_OUT   16
#define CAP     128      // max in-degree capacity (Poisson(16): max ~45 over 100k)

// Scratch (__device__ globals; allocation-free rule)
__device__ __align__(16) int     g_deg   [N_NODES];
__device__ __align__(16) int     g_bucket[N_NODES * CAP];   // incoming src ids
__device__ __align__(16) float   g_dinv  [N_NODES];
__device__ __align__(16) __half2 g_h1h   [N_NODES * 32];    // dinv*(x@W1), fp16
__device__ __align__(16) __half2 g_hrh   [N_NODES * 32];    // relu(layer-1), fp16
__device__ __align__(16) __half2 g_h2h   [N_NODES * 8];     // dinv*(hrelu@W2), fp16

__device__ __forceinline__ __half2 as_h2(int v) { return *reinterpret_cast<__half2*>(&v); }

#define FFMA2(d, a, b, c) \
    asm("fma.rn.f32x2 %0, %1, %2, %3;" : "=l"(d) : "l"(a), "l"(b), "l"(c))

// ---------------------------------------------------------------------------
__global__ void k_zero() {
    int i = blockIdx.x * blockDim.x + threadIdx.x;
    if (i < N_NODES / 4) ((int4*)g_deg)[i] = make_int4(0, 0, 0, 0);
}

// single-pass CSR build: 8 edges per thread (MLP=8 hides ATOMG latency)
__global__ void k_build(const int* __restrict__ ei) {
    int t = blockIdx.x * blockDim.x + threadIdx.x;
    if (t >= N_EDGES / 8) return;
    const int4* s4 = (const int4*)ei;
    const int4* d4 = (const int4*)(ei + N_EDGES);
    int4 sa = s4[2 * t], sb = s4[2 * t + 1];
    int4 da = d4[2 * t], db = d4[2 * t + 1];
    int p0 = atomicAdd(&g_deg[da.x], 1);
    int p1 = atomicAdd(&g_deg[da.y], 1);
    int p2 = atomicAdd(&g_deg[da.z], 1);
    int p3 = atomicAdd(&g_deg[da.w], 1);
    int p4 = atomicAdd(&g_deg[db.x], 1);
    int p5 = atomicAdd(&g_deg[db.y], 1);
    int p6 = atomicAdd(&g_deg[db.z], 1);
    int p7 = atomicAdd(&g_deg[db.w], 1);
    if (p0 < CAP) g_bucket[da.x * CAP + p0] = sa.x;
    if (p1 < CAP) g_bucket[da.y * CAP + p1] = sa.y;
    if (p2 < CAP) g_bucket[da.z * CAP + p2] = sa.z;
    if (p3 < CAP) g_bucket[da.w * CAP + p3] = sa.w;
    if (p4 < CAP) g_bucket[db.x * CAP + p4] = sb.x;
    if (p5 < CAP) g_bucket[db.y * CAP + p5] = sb.y;
    if (p6 < CAP) g_bucket[db.z * CAP + p6] = sb.z;
    if (p7 < CAP) g_bucket[db.w * CAP + p7] = sb.w;
}

// h1h = half2(dinv * (x @ W1)); packed-f32x2 FFMA2 inner loop.
// 32 rows/block, threads (32,8): tx -> col pair f0=2tx, ty -> 4 rows.
__global__ void k_gemm1(const float* __restrict__ x, const float* __restrict__ W1) {
    __shared__ float  Ws[64 * 64];      // W1, row-major; col pairs 8B-aligned
    __shared__ float2 xs2[32][64];      // x duplicated: (v, v)
    int tx = threadIdx.x, ty = threadIdx.y;
    int tid = ty * 32 + tx;
    for (int k = tid; k < 64 * 64; k += 256) Ws[k] = W1[k];
    int row0 = blockIdx.x * 32;                      // 100000 % 32 == 0
    for (int k = tid; k < 32 * 64; k += 256) {
        float v = x[row0 * 64 + k];
        xs2[k >> 6][k & 63] = make_float2(v, v);
    }
    __syncthreads();
    int f0 = tx * 2;
    unsigned long long a0 = 0ull, a1 = 0ull, a2 = 0ull, a3 = 0ull;
#pragma unroll
    for (int k = 0; k < 64; k++) {
        unsigned long long w  = *(const unsigned long long*)&Ws[k * 64 + f0];
        unsigned long long x0 = *(const unsigned long long*)&xs2[ty][k];
        unsigned long long x1 = *(const unsigned long long*)&xs2[ty + 8][k];
        unsigned long long x2 = *(const unsigned long long*)&xs2[ty + 16][k];
        unsigned long long x3 = *(const unsigned long long*)&xs2[ty + 24][k];
        FFMA2(a0, x0, w, a0);
        FFMA2(a1, x1, w, a1);
        FFMA2(a2, x2, w, a2);
        FFMA2(a3, x3, w, a3);
    }
    unsigned long long av[4] = {a0, a1, a2, a3};
#pragma unroll
    for (int q = 0; q < 4; q++) {
        int r = row0 + ty + q * 8;
        float di = rsqrtf((float)(g_deg[r] + 1));
        if (tx == (r & 31)) g_dinv[r] = di;
        float lo, hi;
        asm("mov.b64 {%0, %1}, %2;" : "=f"(lo), "=f"(hi) : "l"(av[q]));
        g_h1h[r * 32 + tx] = __floats2half2_rn(lo * di, hi * di);
    }
}

// layer-1 pull + relu. 8 lanes/node (LDG.128 = 4x half2), 32 nodes/block.
// 4-edge fp16 reduction tree, fp32 accumulate per quad. Output fp16.
__global__ void k_agg1(const float* __restrict__ b1) {
    int d = blockIdx.x * 32 + (threadIdx.x >> 3);
    if (d >= N_NODES) return;
    int lane = threadIdx.x & 7;
    int deg = g_deg[d]; if (deg > CAP) deg = CAP;
    const int* bk = &g_bucket[d * CAP];

    float acc[8];
    {   // self-loop
        int4 v = ((const int4*)(g_h1h + d * 32))[lane];
        float2 f0 = __half22float2(as_h2(v.x));
        float2 f1 = __half22float2(as_h2(v.y));
        float2 f2 = __half22float2(as_h2(v.z));
        float2 f3 = __half22float2(as_h2(v.w));
        acc[0] = f0.x; acc[1] = f0.y; acc[2] = f1.x; acc[3] = f1.y;
        acc[4] = f2.x; acc[5] = f2.y; acc[6] = f3.x; acc[7] = f3.y;
    }
    int j = 0;
    for (; j + 3 < deg; j += 4) {
        int s0 = bk[j], s1 = bk[j + 1], s2 = bk[j + 2], s3 = bk[j + 3];
        int4 v0 = ((const int4*)(g_h1h + s0 * 32))[lane];
        int4 v1 = ((const int4*)(g_h1h + s1 * 32))[lane];
        int4 v2 = ((const int4*)(g_h1h + s2 * 32))[lane];
        int4 v3 = ((const int4*)(g_h1h + s3 * 32))[lane];
        __half2 p0 = __hadd2(__hadd2(as_h2(v0.x), as_h2(v1.x)), __hadd2(as_h2(v2.x), as_h2(v3.x)));
        __half2 p1 = __hadd2(__hadd2(as_h2(v0.y), as_h2(v1.y)), __hadd2(as_h2(v2.y), as_h2(v3.y)));
        __half2 p2 = __hadd2(__hadd2(as_h2(v0.z), as_h2(v1.z)), __hadd2(as_h2(v2.z), as_h2(v3.z)));
        __half2 p3 = __hadd2(__hadd2(as_h2(v0.w), as_h2(v1.w)), __hadd2(as_h2(v2.w), as_h2(v3.w)));
        float2 f0 = __half22float2(p0);
        float2 f1 = __half22float2(p1);
        float2 f2 = __half22float2(p2);
        float2 f3 = __half22float2(p3);
        acc[0] += f0.x; acc[1] += f0.y; acc[2] += f1.x; acc[3] += f1.y;
        acc[4] += f2.x; acc[5] += f2.y; acc[6] += f3.x; acc[7] += f3.y;
    }
    if (j + 1 < deg) {
        int s0 = bk[j], s1 = bk[j + 1];
        j += 2;
        int4 v0 = ((const int4*)(g_h1h + s0 * 32))[lane];
        int4 v1 = ((const int4*)(g_h1h + s1 * 32))[lane];
        float2 f0 = __half22float2(__hadd2(as_h2(v0.x), as_h2(v1.x)));
        float2 f1 = __half22float2(__hadd2(as_h2(v0.y), as_h2(v1.y)));
        float2 f2 = __half22float2(__hadd2(as_h2(v0.z), as_h2(v1.z)));
        float2 f3 = __half22float2(__hadd2(as_h2(v0.w), as_h2(v1.w)));
        acc[0] += f0.x; acc[1] += f0.y; acc[2] += f1.x; acc[3] += f1.y;
        acc[4] += f2.x; acc[5] += f2.y; acc[6] += f3.x; acc[7] += f3.y;
    }
    if (j < deg) {
        int4 v = ((const int4*)(g_h1h + bk[j] * 32))[lane];
        float2 f0 = __half22float2(as_h2(v.x));
        float2 f1 = __half22float2(as_h2(v.y));
        float2 f2 = __half22float2(as_h2(v.z));
        float2 f3 = __half22float2(as_h2(v.w));
        acc[0] += f0.x; acc[1] += f0.y; acc[2] += f1.x; acc[3] += f1.y;
        acc[4] += f2.x; acc[5] += f2.y; acc[6] += f3.x; acc[7] += f3.y;
    }
    float sc = g_dinv[d];
    float4 bA = ((const float4*)b1)[lane * 2];
    float4 bB = ((const float4*)b1)[lane * 2 + 1];
    float r0 = fmaxf(fmaf(acc[0], sc, bA.x), 0.f);
    float r1 = fmaxf(fmaf(acc[1], sc, bA.y), 0.f);
    float r2 = fmaxf(fmaf(acc[2], sc, bA.z), 0.f);
    float r3 = fmaxf(fmaf(acc[3], sc, bA.w), 0.f);
    float r4 = fmaxf(fmaf(acc[4], sc, bB.x), 0.f);
    float r5 = fmaxf(fmaf(acc[5], sc, bB.y), 0.f);
    float r6 = fmaxf(fmaf(acc[6], sc, bB.z), 0.f);
    float r7 = fmaxf(fmaf(acc[7], sc, bB.w), 0.f);
    __half2 h0 = __floats2half2_rn(r0, r1);
    __half2 h1 = __floats2half2_rn(r2, r3);
    __half2 h2 = __floats2half2_rn(r4, r5);
    __half2 h3 = __floats2half2_rn(r6, r7);
    int4 o;
    o.x = *(int*)&h0; o.y = *(int*)&h1; o.z = *(int*)&h2; o.w = *(int*)&h3;
    ((int4*)(g_hrh + d * 32))[lane] = o;
}

// h2h = half2(dinv * (hrelu_fp16 @ W2)). 16 rows/block, block (16,16).
__global__ void k_gemm2(const float* __restrict__ W2) {
    __shared__ float Ws[64 * 16];
    __shared__ float hs[16][64];
    int f = threadIdx.x;   // 0..15 (output feature)
    int r = threadIdx.y;   // 0..15 (row)
    int tid = r * 16 + f;
    for (int k = tid; k < 64 * 16; k += 256) Ws[k] = W2[k];
    int row0 = blockIdx.x * 16;
    for (int k = tid; k < 16 * 32; k += 256) {           // 512 half2 loads
        float2 v = __half22float2(g_hrh[row0 * 32 + k]);
        hs[k >> 5][(k & 31) * 2    ] = v.x;
        hs[k >> 5][(k & 31) * 2 + 1] = v.y;
    }
    __syncthreads();
    float acc = 0.f;
#pragma unroll
    for (int k = 0; k < 64; k++) acc = fmaf(hs[r][k], Ws[k * 16 + f], acc);
    int row = row0 + r;
    ((__half*)g_h2h)[row * 16 + f] = __float2half(acc * g_dinv[row]);
}

// layer-2 pull + bias + log_softmax. 4 lanes/node (LDG.64), 64 nodes/block.
__global__ void k_agg2(const float* __restrict__ b2, float* __restrict__ out) {
    int d = blockIdx.x * 64 + (threadIdx.x >> 2);
    if (d >= N_NODES) return;
    int lane = threadIdx.x & 3;
    int deg = g_deg[d]; if (deg > CAP) deg = CAP;
    const int* bk = &g_bucket[d * CAP];

    float acc[4];
    {
        int2 v = ((const int2*)(g_h2h + d * 8))[lane];
        float2 f0 = __half22float2(as_h2(v.x));
        float2 f1 = __half22float2(as_h2(v.y));
        acc[0] = f0.x; acc[1] = f0.y; acc[2] = f1.x; acc[3] = f1.y;
    }
    int j = 0;
    for (; j + 3 < deg; j += 4) {
        int s0 = bk[j], s1 = bk[j + 1], s2 = bk[j + 2], s3 = bk[j + 3];
        int2 v0 = ((const int2*)(g_h2h + s0 * 8))[lane];
        int2 v1 = ((const int2*)(g_h2h + s1 * 8))[lane];
        int2 v2 = ((const int2*)(g_h2h + s2 * 8))[lane];
        int2 v3 = ((const int2*)(g_h2h + s3 * 8))[lane];
        __half2 p0 = __hadd2(__hadd2(as_h2(v0.x), as_h2(v1.x)), __hadd2(as_h2(v2.x), as_h2(v3.x)));
        __half2 p1 = __hadd2(__hadd2(as_h2(v0.y), as_h2(v1.y)), __hadd2(as_h2(v2.y), as_h2(v3.y)));
        float2 f0 = __half22float2(p0);
        float2 f1 = __half22float2(p1);
        acc[0] += f0.x; acc[1] += f0.y; acc[2] += f1.x; acc[3] += f1.y;
    }
    if (j + 1 < deg) {
        int s0 = bk[j], s1 = bk[j + 1];
        j += 2;
        int2 v0 = ((const int2*)(g_h2h + s0 * 8))[lane];
        int2 v1 = ((const int2*)(g_h2h + s1 * 8))[lane];
        float2 f0 = __half22float2(__hadd2(as_h2(v0.x), as_h2(v1.x)));
        float2 f1 = __half22float2(__hadd2(as_h2(v0.y), as_h2(v1.y)));
        acc[0] += f0.x; acc[1] += f0.y; acc[2] += f1.x; acc[3] += f1.y;
    }
    if (j < deg) {
        int2 v = ((const int2*)(g_h2h + bk[j] * 8))[lane];
        float2 f0 = __half22float2(as_h2(v.x));
        float2 f1 = __half22float2(as_h2(v.y));
        acc[0] += f0.x; acc[1] += f0.y; acc[2] += f1.x; acc[3] += f1.y;
    }
    float sc = g_dinv[d];
    float4 b = ((const float4*)b2)[lane];
    float y0 = fmaf(acc[0], sc, b.x);
    float y1 = fmaf(acc[1], sc, b.y);
    float y2 = fmaf(acc[2], sc, b.z);
    float y3 = fmaf(acc[3], sc, b.w);
    float m = fmaxf(fmaxf(y0, y1), fmaxf(y2, y3));
    m = fmaxf(m, __shfl_xor_sync(0xffffffffu, m, 1, 4));
    m = fmaxf(m, __shfl_xor_sync(0xffffffffu, m, 2, 4));
    float s = expf(y0 - m) + expf(y1 - m) + expf(y2 - m) + expf(y3 - m);
    s += __shfl_xor_sync(0xffffffffu, s, 1, 4);
    s += __shfl_xor_sync(0xffffffffu, s, 2, 4);
    float lse = m + logf(s);
    float4 o = make_float4(y0 - lse, y1 - lse, y2 - lse, y3 - lse);
    ((float4*)&out[d * 16])[lane] = o;
}

extern "C" void kernel_launch(void* const* d_in, const int* in_sizes, int n_in,
                              void* d_out, int out_size) {
    const float* x  = (const float*)d_in[0];
    const int*   ei = (const int*)d_in[1];     // int32 [2, E]
    const float* W1 = (const float*)d_in[2];
    const float* b1 = (const float*)d_in[3];
    const float* W2 = (const float*)d_in[4];
    const float* b2 = (const float*)d_in[5];
    float*       out = (float*)d_out;

    const int TB = 256;

    k_zero  <<<(N_NODES / 4 + TB - 1) / TB, TB>>>();
    k_build <<<(N_EDGES / 8 + TB - 1) / TB, TB>>>(ei);
    k_gemm1 <<<N_NODES / 32, dim3(32, 8)>>>(x, W1);
    k_agg1  <<<(N_NODES + 31) / 32, TB>>>(b1);
    k_gemm2 <<<N_NODES / 16, dim3(16, 16)>>>(W2);
    k_agg2  <<<(N_NODES + 63) / 64, TB>>>(b2, out);
}

// round 10
// speedup vs baseline: 1.2716x; 1.2716x over previous
#include <cuda_runtime.h>
#include <cuda_fp16.h>

#define N_NODES 100000
#define N_EDGES 1600000
#define D_HID   64
#define D_OUT   16
#define CAP     128      // max in-degree capacity (Poisson(16): max ~45 over 100k)

// Scratch (__device__ globals; allocation-free rule)
__device__ __align__(16) int     g_deg   [N_NODES];
__device__ __align__(16) int     g_bucket[N_NODES * CAP];   // incoming src ids
__device__ __align__(16) float   g_dinv  [N_NODES];
__device__ __align__(16) __half2 g_h1h   [N_NODES * 32];    // dinv*(x@W1), fp16
__device__ __align__(16) __half2 g_hrh   [N_NODES * 32];    // relu(layer-1), fp16
__device__ __align__(16) __half2 g_h2h   [N_NODES * 8];     // dinv*(hrelu@W2), fp16

__device__ __forceinline__ __half2 as_h2(int v) { return *reinterpret_cast<__half2*>(&v); }

// ---------------------------------------------------------------------------
__global__ void k_zero() {
    int i = blockIdx.x * blockDim.x + threadIdx.x;
    if (i < N_NODES / 4) ((int4*)g_deg)[i] = make_int4(0, 0, 0, 0);
}

// single-pass CSR build: 4 edges per thread
__global__ void k_build(const int* __restrict__ ei) {
    int t = blockIdx.x * blockDim.x + threadIdx.x;
    if (t >= N_EDGES / 4) return;
    int4 sv = ((const int4*)ei)[t];
    int4 dv = ((const int4*)(ei + N_EDGES))[t];
    int p;
    p = atomicAdd(&g_deg[dv.x], 1); if (p < CAP) g_bucket[dv.x * CAP + p] = sv.x;
    p = atomicAdd(&g_deg[dv.y], 1); if (p < CAP) g_bucket[dv.y * CAP + p] = sv.y;
    p = atomicAdd(&g_deg[dv.z], 1); if (p < CAP) g_bucket[dv.z * CAP + p] = sv.z;
    p = atomicAdd(&g_deg[dv.w], 1); if (p < CAP) g_bucket[dv.w * CAP + p] = sv.w;
}

// h1h = half2(dinv * (x @ W1)); also computes+stores dinv (each row hit once).
__global__ void k_gemm1(const float* __restrict__ x, const float* __restrict__ W1) {
    __shared__ float Ws[64 * 64];
    __shared__ float xs[32][64];
    int tx = threadIdx.x, ty = threadIdx.y;
    int tid = ty * 32 + tx;
    for (int k = tid; k < 64 * 64; k += 256) Ws[k] = W1[k];
    int row0 = blockIdx.x * 32;                      // 100000 % 32 == 0
    for (int k = tid; k < 32 * 64; k += 256) xs[k >> 6][k & 63] = x[row0 * 64 + k];
    __syncthreads();
    int f0 = tx * 2;
    float a0x = 0, a0y = 0, a1x = 0, a1y = 0, a2x = 0, a2y = 0, a3x = 0, a3y = 0;
#pragma unroll
    for (int k = 0; k < 64; k++) {
        float2 w = *(const float2*)&Ws[k * 64 + f0];
        float x0 = xs[ty][k], x1 = xs[ty + 8][k], x2 = xs[ty + 16][k], x3 = xs[ty + 24][k];
        a0x = fmaf(x0, w.x, a0x); a0y = fmaf(x0, w.y, a0y);
        a1x = fmaf(x1, w.x, a1x); a1y = fmaf(x1, w.y, a1y);
        a2x = fmaf(x2, w.x, a2x); a2y = fmaf(x2, w.y, a2y);
        a3x = fmaf(x3, w.x, a3x); a3y = fmaf(x3, w.y, a3y);
    }
#pragma unroll
    for (int q = 0; q < 4; q++) {
        int r = row0 + ty + q * 8;
        float di = rsqrtf((float)(g_deg[r] + 1));
        if (tx == (r & 31)) g_dinv[r] = di;
        float ax = (q == 0 ? a0x : q == 1 ? a1x : q == 2 ? a2x : a3x);
        float ay = (q == 0 ? a0y : q == 1 ? a1y : q == 2 ? a2y : a3y);
        g_h1h[r * 32 + tx] = __floats2half2_rn(ax * di, ay * di);
    }
}

// layer-1 pull + relu. 8 lanes/node (LDG.128 = 4x half2), 32 nodes/block.
// 4-edge fp16 reduction tree, fp32 accumulate per quad. Output fp16.
__global__ void k_agg1(const float* __restrict__ b1) {
    int d = blockIdx.x * 32 + (threadIdx.x >> 3);
    if (d >= N_NODES) return;
    int lane = threadIdx.x & 7;
    int deg = g_deg[d]; if (deg > CAP) deg = CAP;
    const int* bk = &g_bucket[d * CAP];

    float acc[8];
    {   // self-loop
        int4 v = ((const int4*)(g_h1h + d * 32))[lane];
        float2 f0 = __half22float2(as_h2(v.x));
        float2 f1 = __half22float2(as_h2(v.y));
        float2 f2 = __half22float2(as_h2(v.z));
        float2 f3 = __half22float2(as_h2(v.w));
        acc[0] = f0.x; acc[1] = f0.y; acc[2] = f1.x; acc[3] = f1.y;
        acc[4] = f2.x; acc[5] = f2.y; acc[6] = f3.x; acc[7] = f3.y;
    }
    int j = 0;
    for (; j + 3 < deg; j += 4) {
        int s0 = bk[j], s1 = bk[j + 1], s2 = bk[j + 2], s3 = bk[j + 3];
        int4 v0 = ((const int4*)(g_h1h + s0 * 32))[lane];
        int4 v1 = ((const int4*)(g_h1h + s1 * 32))[lane];
        int4 v2 = ((const int4*)(g_h1h + s2 * 32))[lane];
        int4 v3 = ((const int4*)(g_h1h + s3 * 32))[lane];
        __half2 p0 = __hadd2(__hadd2(as_h2(v0.x), as_h2(v1.x)), __hadd2(as_h2(v2.x), as_h2(v3.x)));
        __half2 p1 = __hadd2(__hadd2(as_h2(v0.y), as_h2(v1.y)), __hadd2(as_h2(v2.y), as_h2(v3.y)));
        __half2 p2 = __hadd2(__hadd2(as_h2(v0.z), as_h2(v1.z)), __hadd2(as_h2(v2.z), as_h2(v3.z)));
        __half2 p3 = __hadd2(__hadd2(as_h2(v0.w), as_h2(v1.w)), __hadd2(as_h2(v2.w), as_h2(v3.w)));
        float2 f0 = __half22float2(p0);
        float2 f1 = __half22float2(p1);
        float2 f2 = __half22float2(p2);
        float2 f3 = __half22float2(p3);
        acc[0] += f0.x; acc[1] += f0.y; acc[2] += f1.x; acc[3] += f1.y;
        acc[4] += f2.x; acc[5] += f2.y; acc[6] += f3.x; acc[7] += f3.y;
    }
    if (j + 1 < deg) {
        int s0 = bk[j], s1 = bk[j + 1];
        j += 2;
        int4 v0 = ((const int4*)(g_h1h + s0 * 32))[lane];
        int4 v1 = ((const int4*)(g_h1h + s1 * 32))[lane];
        float2 f0 = __half22float2(__hadd2(as_h2(v0.x), as_h2(v1.x)));
        float2 f1 = __half22float2(__hadd2(as_h2(v0.y), as_h2(v1.y)));
        float2 f2 = __half22float2(__hadd2(as_h2(v0.z), as_h2(v1.z)));
        float2 f3 = __half22float2(__hadd2(as_h2(v0.w), as_h2(v1.w)));
        acc[0] += f0.x; acc[1] += f0.y; acc[2] += f1.x; acc[3] += f1.y;
        acc[4] += f2.x; acc[5] += f2.y; acc[6] += f3.x; acc[7] += f3.y;
    }
    if (j < deg) {
        int4 v = ((const int4*)(g_h1h + bk[j] * 32))[lane];
        float2 f0 = __half22float2(as_h2(v.x));
        float2 f1 = __half22float2(as_h2(v.y));
        float2 f2 = __half22float2(as_h2(v.z));
        float2 f3 = __half22float2(as_h2(v.w));
        acc[0] += f0.x; acc[1] += f0.y; acc[2] += f1.x; acc[3] += f1.y;
        acc[4] += f2.x; acc[5] += f2.y; acc[6] += f3.x; acc[7] += f3.y;
    }
    float sc = g_dinv[d];
    float4 bA = ((const float4*)b1)[lane * 2];
    float4 bB = ((const float4*)b1)[lane * 2 + 1];
    float r0 = fmaxf(fmaf(acc[0], sc, bA.x), 0.f);
    float r1 = fmaxf(fmaf(acc[1], sc, bA.y), 0.f);
    float r2 = fmaxf(fmaf(acc[2], sc, bA.z), 0.f);
    float r3 = fmaxf(fmaf(acc[3], sc, bA.w), 0.f);
    float r4 = fmaxf(fmaf(acc[4], sc, bB.x), 0.f);
    float r5 = fmaxf(fmaf(acc[5], sc, bB.y), 0.f);
    float r6 = fmaxf(fmaf(acc[6], sc, bB.z), 0.f);
    float r7 = fmaxf(fmaf(acc[7], sc, bB.w), 0.f);
    __half2 h0 = __floats2half2_rn(r0, r1);
    __half2 h1 = __floats2half2_rn(r2, r3);
    __half2 h2 = __floats2half2_rn(r4, r5);
    __half2 h3 = __floats2half2_rn(r6, r7);
    int4 o;
    o.x = *(int*)&h0; o.y = *(int*)&h1; o.z = *(int*)&h2; o.w = *(int*)&h3;
    ((int4*)(g_hrh + d * 32))[lane] = o;
}

// h2h = half2(dinv * (hrelu_fp16 @ W2)). 64 rows/block, block (16,16),
// 4 rows per thread: W2 smem-load traffic amortized 4x vs 16-row blocks.
__global__ void k_gemm2(const float* __restrict__ W2) {
    __shared__ float Ws[64 * 16];
    __shared__ float hs[64][64];
    int f = threadIdx.x;   // 0..15 (output feature)
    int r = threadIdx.y;   // 0..15 (row group)
    int tid = r * 16 + f;
    for (int k = tid; k < 64 * 16; k += 256) Ws[k] = W2[k];
    int row0 = blockIdx.x * 64;                    // 100000 % 64 != 0 -> guard
    int nrows = N_NODES - row0; if (nrows > 64) nrows = 64;
    for (int k = tid; k < nrows * 32; k += 256) {  // half2 loads
        float2 v = __half22float2(g_hrh[row0 * 32 + k]);
        hs[k >> 5][(k & 31) * 2    ] = v.x;
        hs[k >> 5][(k & 31) * 2 + 1] = v.y;
    }
    __syncthreads();
    float a0 = 0.f, a1 = 0.f, a2 = 0.f, a3 = 0.f;
#pragma unroll
    for (int k = 0; k < 64; k++) {
        float w = Ws[k * 16 + f];
        a0 = fmaf(hs[r     ][k], w, a0);
        a1 = fmaf(hs[r + 16][k], w, a1);
        a2 = fmaf(hs[r + 32][k], w, a2);
        a3 = fmaf(hs[r + 48][k], w, a3);
    }
    float av[4] = {a0, a1, a2, a3};
#pragma unroll
    for (int q = 0; q < 4; q++) {
        int row = row0 + r + q * 16;
        if (row < N_NODES)
            ((__half*)g_h2h)[row * 16 + f] = __float2half(av[q] * g_dinv[row]);
    }
}

// layer-2 pull + bias + log_softmax. 4 lanes/node (LDG.64), 64 nodes/block.
__global__ void k_agg2(const float* __restrict__ b2, float* __restrict__ out) {
    int d = blockIdx.x * 64 + (threadIdx.x >> 2);
    if (d >= N_NODES) return;
    int lane = threadIdx.x & 3;
    int deg = g_deg[d]; if (deg > CAP) deg = CAP;
    const int* bk = &g_bucket[d * CAP];

    float acc[4];
    {
        int2 v = ((const int2*)(g_h2h + d * 8))[lane];
        float2 f0 = __half22float2(as_h2(v.x));
        float2 f1 = __half22float2(as_h2(v.y));
        acc[0] = f0.x; acc[1] = f0.y; acc[2] = f1.x; acc[3] = f1.y;
    }
    int j = 0;
    for (; j + 3 < deg; j += 4) {
        int s0 = bk[j], s1 = bk[j + 1], s2 = bk[j + 2], s3 = bk[j + 3];
        int2 v0 = ((const int2*)(g_h2h + s0 * 8))[lane];
        int2 v1 = ((const int2*)(g_h2h + s1 * 8))[lane];
        int2 v2 = ((const int2*)(g_h2h + s2 * 8))[lane];
        int2 v3 = ((const int2*)(g_h2h + s3 * 8))[lane];
        __half2 p0 = __hadd2(__hadd2(as_h2(v0.x), as_h2(v1.x)), __hadd2(as_h2(v2.x), as_h2(v3.x)));
        __half2 p1 = __hadd2(__hadd2(as_h2(v0.y), as_h2(v1.y)), __hadd2(as_h2(v2.y), as_h2(v3.y)));
        float2 f0 = __half22float2(p0);
        float2 f1 = __half22float2(p1);
        acc[0] += f0.x; acc[1] += f0.y; acc[2] += f1.x; acc[3] += f1.y;
    }
    if (j + 1 < deg) {
        int s0 = bk[j], s1 = bk[j + 1];
        j += 2;
        int2 v0 = ((const int2*)(g_h2h + s0 * 8))[lane];
        int2 v1 = ((const int2*)(g_h2h + s1 * 8))[lane];
        float2 f0 = __half22float2(__hadd2(as_h2(v0.x), as_h2(v1.x)));
        float2 f1 = __half22float2(__hadd2(as_h2(v0.y), as_h2(v1.y)));
        acc[0] += f0.x; acc[1] += f0.y; acc[2] += f1.x; acc[3] += f1.y;
    }
    if (j < deg) {
        int2 v = ((const int2*)(g_h2h + bk[j] * 8))[lane];
        float2 f0 = __half22float2(as_h2(v.x));
        float2 f1 = __half22float2(as_h2(v.y));
        acc[0] += f0.x; acc[1] += f0.y; acc[2] += f1.x; acc[3] += f1.y;
    }
    float sc = g_dinv[d];
    float4 b = ((const float4*)b2)[lane];
    float y0 = fmaf(acc[0], sc, b.x);
    float y1 = fmaf(acc[1], sc, b.y);
    float y2 = fmaf(acc[2], sc, b.z);
    float y3 = fmaf(acc[3], sc, b.w);
    float m = fmaxf(fmaxf(y0, y1), fmaxf(y2, y3));
    m = fmaxf(m, __shfl_xor_sync(0xffffffffu, m, 1, 4));
    m = fmaxf(m, __shfl_xor_sync(0xffffffffu, m, 2, 4));
    float s = expf(y0 - m) + expf(y1 - m) + expf(y2 - m) + expf(y3 - m);
    s += __shfl_xor_sync(0xffffffffu, s, 1, 4);
    s += __shfl_xor_sync(0xffffffffu, s, 2, 4);
    float lse = m + logf(s);
    float4 o = make_float4(y0 - lse, y1 - lse, y2 - lse, y3 - lse);
    ((float4*)&out[d * 16])[lane] = o;
}

extern "C" void kernel_launch(void* const* d_in, const int* in_sizes, int n_in,
                              void* d_out, int out_size) {
    const float* x  = (const float*)d_in[0];
    const int*   ei = (const int*)d_in[1];     // int32 [2, E]
    const float* W1 = (const float*)d_in[2];
    const float* b1 = (const float*)d_in[3];
    const float* W2 = (const float*)d_in[4];
    const float* b2 = (const float*)d_in[5];
    float*       out = (float*)d_out;

    const int TB = 256;

    k_zero  <<<(N_NODES / 4 + TB - 1) / TB, TB>>>();
    k_build <<<(N_EDGES / 4 + TB - 1) / TB, TB>>>(ei);
    k_gemm1 <<<N_NODES / 32, dim3(32, 8)>>>(x, W1);
    k_agg1  <<<(N_NODES + 31) / 32, TB>>>(b1);
    k_gemm2 <<<(N_NODES + 63) / 64, dim3(16, 16)>>>(W2);
    k_agg2  <<<(N_NODES + 63) / 64, TB>>>(b2, out);
}

// round 11
// speedup vs baseline: 1.6346x; 1.2855x over previous
#include <cuda_runtime.h>
#include <cuda_fp16.h>

#define N_NODES 100000
#define N_EDGES 1600000
#define D_HID   64
#define D_OUT   16
#define CAP     128      // max in-degree capacity (Poisson(16): max ~45 over 100k)

// Scratch (__device__ globals; allocation-free rule)
__device__ __align__(16) int     g_deg   [N_NODES];
__device__ __align__(16) int     g_bucket[N_NODES * CAP];   // incoming src ids
__device__ __align__(16) float   g_dinv  [N_NODES];
__device__ __align__(16) __half2 g_h1h   [N_NODES * 32];    // dinv*(x@W1), fp16
__device__ __align__(16) __half2 g_hrh   [N_NODES * 32];    // relu(layer-1), fp16
__device__ __align__(16) __half2 g_h2h   [N_NODES * 8];     // dinv*(hrelu@W2), fp16

__device__ __forceinline__ __half2 as_h2(int v) { return *reinterpret_cast<__half2*>(&v); }

// ---------------------------------------------------------------------------
__global__ void k_zero() {
    int i = blockIdx.x * blockDim.x + threadIdx.x;
    if (i < N_NODES / 4) ((int4*)g_deg)[i] = make_int4(0, 0, 0, 0);
}

// single-pass CSR build: 4 edges per thread
__global__ void k_build(const int* __restrict__ ei) {
    int t = blockIdx.x * blockDim.x + threadIdx.x;
    if (t >= N_EDGES / 4) return;
    int4 sv = ((const int4*)ei)[t];
    int4 dv = ((const int4*)(ei + N_EDGES))[t];
    int p;
    p = atomicAdd(&g_deg[dv.x], 1); if (p < CAP) g_bucket[dv.x * CAP + p] = sv.x;
    p = atomicAdd(&g_deg[dv.y], 1); if (p < CAP) g_bucket[dv.y * CAP + p] = sv.y;
    p = atomicAdd(&g_deg[dv.z], 1); if (p < CAP) g_bucket[dv.z * CAP + p] = sv.z;
    p = atomicAdd(&g_deg[dv.w], 1); if (p < CAP) g_bucket[dv.w * CAP + p] = sv.w;
}

// h1h = half2(dinv * (x @ W1)) via tensor-core mma.sync (fp16 in, fp32 accum).
// 128 rows/block, 256 threads = 8 warps x 16 rows. Also stores g_dinv.
__global__ void k_gemm1(const float* __restrict__ x, const float* __restrict__ W1) {
    __shared__ __half xh[128][72];    // 144B row stride: LDSM conflict-free
    __shared__ __half wh[64][72];     // wh[k][n]
    __shared__ float  dinv_s[128];
    int tid = threadIdx.x;
    int row0 = blockIdx.x * 128;

    for (int k = tid; k < 64 * 64; k += 256)
        wh[k >> 6][k & 63] = __float2half(W1[k]);
    for (int k = tid; k < 128 * 64; k += 256) {
        int r = k >> 6, c = k & 63;
        int row = row0 + r;
        xh[r][c] = __float2half(row < N_NODES ? x[row * 64 + c] : 0.f);
    }
    if (tid < 128) {
        int row = row0 + tid;
        if (row < N_NODES) {
            float di = rsqrtf((float)(g_deg[row] + 1));
            dinv_s[tid] = di;
            g_dinv[row] = di;
        }
    }
    __syncthreads();

    int warp = tid >> 5, lane = tid & 31;
    int mrow = warp * 16;

    // A fragments: 4 k-chunks of 16
    unsigned a[4][4];
#pragma unroll
    for (int kc = 0; kc < 4; kc++) {
        unsigned addr = (unsigned)__cvta_generic_to_shared(
            &xh[mrow + (lane & 15)][kc * 16 + (lane >> 4) * 8]);
        asm volatile("ldmatrix.sync.aligned.m8n8.x4.shared.b16 {%0,%1,%2,%3}, [%4];"
                     : "=r"(a[kc][0]), "=r"(a[kc][1]), "=r"(a[kc][2]), "=r"(a[kc][3])
                     : "r"(addr));
    }

    float acc[8][4];
#pragma unroll
    for (int t = 0; t < 8; t++) {
        acc[t][0] = acc[t][1] = acc[t][2] = acc[t][3] = 0.f;
#pragma unroll
        for (int kc = 0; kc < 4; kc++) {
            unsigned b0, b1;
            unsigned baddr = (unsigned)__cvta_generic_to_shared(
                &wh[kc * 16 + (lane & 15)][t * 8]);
            asm volatile("ldmatrix.sync.aligned.m8n8.x2.trans.shared.b16 {%0,%1}, [%2];"
                         : "=r"(b0), "=r"(b1) : "r"(baddr));
            asm volatile("mma.sync.aligned.m16n8k16.row.col.f32.f16.f16.f32 "
                         "{%0,%1,%2,%3}, {%4,%5,%6,%7}, {%8,%9}, {%0,%1,%2,%3};"
                         : "+f"(acc[t][0]), "+f"(acc[t][1]), "+f"(acc[t][2]), "+f"(acc[t][3])
                         : "r"(a[kc][0]), "r"(a[kc][1]), "r"(a[kc][2]), "r"(a[kc][3]),
                           "r"(b0), "r"(b1));
        }
    }

    // Epilogue: C frag rows: r1 = lane/4, r2 = r1+8; col pair = lane%4 within tile
    int r1 = mrow + (lane >> 2);
    int r2 = r1 + 8;
    int gr1 = row0 + r1, gr2 = row0 + r2;
    float di1 = (gr1 < N_NODES) ? dinv_s[r1] : 0.f;
    float di2 = (gr2 < N_NODES) ? dinv_s[r2] : 0.f;
#pragma unroll
    for (int t = 0; t < 8; t++) {
        int cp = t * 4 + (lane & 3);   // half2 index within 32
        if (gr1 < N_NODES)
            g_h1h[gr1 * 32 + cp] = __floats2half2_rn(acc[t][0] * di1, acc[t][1] * di1);
        if (gr2 < N_NODES)
            g_h1h[gr2 * 32 + cp] = __floats2half2_rn(acc[t][2] * di2, acc[t][3] * di2);
    }
}

// layer-1 pull + relu. 8 lanes/node (LDG.128 = 4x half2), 32 nodes/block.
// 4-edge fp16 reduction tree, fp32 accumulate per quad. Output fp16.
__global__ void k_agg1(const float* __restrict__ b1) {
    int d = blockIdx.x * 32 + (threadIdx.x >> 3);
    if (d >= N_NODES) return;
    int lane = threadIdx.x & 7;
    int deg = g_deg[d]; if (deg > CAP) deg = CAP;
    const int* bk = &g_bucket[d * CAP];

    float acc[8];
    {   // self-loop
        int4 v = ((const int4*)(g_h1h + d * 32))[lane];
        float2 f0 = __half22float2(as_h2(v.x));
        float2 f1 = __half22float2(as_h2(v.y));
        float2 f2 = __half22float2(as_h2(v.z));
        float2 f3 = __half22float2(as_h2(v.w));
        acc[0] = f0.x; acc[1] = f0.y; acc[2] = f1.x; acc[3] = f1.y;
        acc[4] = f2.x; acc[5] = f2.y; acc[6] = f3.x; acc[7] = f3.y;
    }
    int j = 0;
    for (; j + 3 < deg; j += 4) {
        int s0 = bk[j], s1 = bk[j + 1], s2 = bk[j + 2], s3 = bk[j + 3];
        int4 v0 = ((const int4*)(g_h1h + s0 * 32))[lane];
        int4 v1 = ((const int4*)(g_h1h + s1 * 32))[lane];
        int4 v2 = ((const int4*)(g_h1h + s2 * 32))[lane];
        int4 v3 = ((const int4*)(g_h1h + s3 * 32))[lane];
        __half2 p0 = __hadd2(__hadd2(as_h2(v0.x), as_h2(v1.x)), __hadd2(as_h2(v2.x), as_h2(v3.x)));
        __half2 p1 = __hadd2(__hadd2(as_h2(v0.y), as_h2(v1.y)), __hadd2(as_h2(v2.y), as_h2(v3.y)));
        __half2 p2 = __hadd2(__hadd2(as_h2(v0.z), as_h2(v1.z)), __hadd2(as_h2(v2.z), as_h2(v3.z)));
        __half2 p3 = __hadd2(__hadd2(as_h2(v0.w), as_h2(v1.w)), __hadd2(as_h2(v2.w), as_h2(v3.w)));
        float2 f0 = __half22float2(p0);
        float2 f1 = __half22float2(p1);
        float2 f2 = __half22float2(p2);
        float2 f3 = __half22float2(p3);
        acc[0] += f0.x; acc[1] += f0.y; acc[2] += f1.x; acc[3] += f1.y;
        acc[4] += f2.x; acc[5] += f2.y; acc[6] += f3.x; acc[7] += f3.y;
    }
    if (j + 1 < deg) {
        int s0 = bk[j], s1 = bk[j + 1];
        j += 2;
        int4 v0 = ((const int4*)(g_h1h + s0 * 32))[lane];
        int4 v1 = ((const int4*)(g_h1h + s1 * 32))[lane];
        float2 f0 = __half22float2(__hadd2(as_h2(v0.x), as_h2(v1.x)));
        float2 f1 = __half22float2(__hadd2(as_h2(v0.y), as_h2(v1.y)));
        float2 f2 = __half22float2(__hadd2(as_h2(v0.z), as_h2(v1.z)));
        float2 f3 = __half22float2(__hadd2(as_h2(v0.w), as_h2(v1.w)));
        acc[0] += f0.x; acc[1] += f0.y; acc[2] += f1.x; acc[3] += f1.y;
        acc[4] += f2.x; acc[5] += f2.y; acc[6] += f3.x; acc[7] += f3.y;
    }
    if (j < deg) {
        int4 v = ((const int4*)(g_h1h + bk[j] * 32))[lane];
        float2 f0 = __half22float2(as_h2(v.x));
        float2 f1 = __half22float2(as_h2(v.y));
        float2 f2 = __half22float2(as_h2(v.z));
        float2 f3 = __half22float2(as_h2(v.w));
        acc[0] += f0.x; acc[1] += f0.y; acc[2] += f1.x; acc[3] += f1.y;
        acc[4] += f2.x; acc[5] += f2.y; acc[6] += f3.x; acc[7] += f3.y;
    }
    float sc = g_dinv[d];
    float4 bA = ((const float4*)b1)[lane * 2];
    float4 bB = ((const float4*)b1)[lane * 2 + 1];
    float r0 = fmaxf(fmaf(acc[0], sc, bA.x), 0.f);
    float r1 = fmaxf(fmaf(acc[1], sc, bA.y), 0.f);
    float r2 = fmaxf(fmaf(acc[2], sc, bA.z), 0.f);
    float r3 = fmaxf(fmaf(acc[3], sc, bA.w), 0.f);
    float r4 = fmaxf(fmaf(acc[4], sc, bB.x), 0.f);
    float r5 = fmaxf(fmaf(acc[5], sc, bB.y), 0.f);
    float r6 = fmaxf(fmaf(acc[6], sc, bB.z), 0.f);
    float r7 = fmaxf(fmaf(acc[7], sc, bB.w), 0.f);
    __half2 h0 = __floats2half2_rn(r0, r1);
    __half2 h1 = __floats2half2_rn(r2, r3);
    __half2 h2 = __floats2half2_rn(r4, r5);
    __half2 h3 = __floats2half2_rn(r6, r7);
    int4 o;
    o.x = *(int*)&h0; o.y = *(int*)&h1; o.z = *(int*)&h2; o.w = *(int*)&h3;
    ((int4*)(g_hrh + d * 32))[lane] = o;
}

// h2h = half2(dinv * (hrelu_fp16 @ W2)). 64 rows/block, block (16,16).
__global__ void k_gemm2(const float* __restrict__ W2) {
    __shared__ float Ws[64 * 16];
    __shared__ float hs[64][64];
    int f = threadIdx.x;
    int r = threadIdx.y;
    int tid = r * 16 + f;
    for (int k = tid; k < 64 * 16; k += 256) Ws[k] = W2[k];
    int row0 = blockIdx.x * 64;
    int nrows = N_NODES - row0; if (nrows > 64) nrows = 64;
    for (int k = tid; k < nrows * 32; k += 256) {
        float2 v = __half22float2(g_hrh[row0 * 32 + k]);
        hs[k >> 5][(k & 31) * 2    ] = v.x;
        hs[k >> 5][(k & 31) * 2 + 1] = v.y;
    }
    __syncthreads();
    float a0 = 0.f, a1 = 0.f, a2 = 0.f, a3 = 0.f;
#pragma unroll
    for (int k = 0; k < 64; k++) {
        float w = Ws[k * 16 + f];
        a0 = fmaf(hs[r     ][k], w, a0);
        a1 = fmaf(hs[r + 16][k], w, a1);
        a2 = fmaf(hs[r + 32][k], w, a2);
        a3 = fmaf(hs[r + 48][k], w, a3);
    }
    float av[4] = {a0, a1, a2, a3};
#pragma unroll
    for (int q = 0; q < 4; q++) {
        int row = row0 + r + q * 16;
        if (row < N_NODES)
            ((__half*)g_h2h)[row * 16 + f] = __float2half(av[q] * g_dinv[row]);
    }
}

// layer-2 pull + bias + log_softmax. 4 lanes/node (LDG.64), 64 nodes/block.
__global__ void k_agg2(const float* __restrict__ b2, float* __restrict__ out) {
    int d = blockIdx.x * 64 + (threadIdx.x >> 2);
    if (d >= N_NODES) return;
    int lane = threadIdx.x & 3;
    int deg = g_deg[d]; if (deg > CAP) deg = CAP;
    const int* bk = &g_bucket[d * CAP];

    float acc[4];
    {
        int2 v = ((const int2*)(g_h2h + d * 8))[lane];
        float2 f0 = __half22float2(as_h2(v.x));
        float2 f1 = __half22float2(as_h2(v.y));
        acc[0] = f0.x; acc[1] = f0.y; acc[2] = f1.x; acc[3] = f1.y;
    }
    int j = 0;
    for (; j + 3 < deg; j += 4) {
        int s0 = bk[j], s1 = bk[j + 1], s2 = bk[j + 2], s3 = bk[j + 3];
        int2 v0 = ((const int2*)(g_h2h + s0 * 8))[lane];
        int2 v1 = ((const int2*)(g_h2h + s1 * 8))[lane];
        int2 v2 = ((const int2*)(g_h2h + s2 * 8))[lane];
        int2 v3 = ((const int2*)(g_h2h + s3 * 8))[lane];
        __half2 p0 = __hadd2(__hadd2(as_h2(v0.x), as_h2(v1.x)), __hadd2(as_h2(v2.x), as_h2(v3.x)));
        __half2 p1 = __hadd2(__hadd2(as_h2(v0.y), as_h2(v1.y)), __hadd2(as_h2(v2.y), as_h2(v3.y)));
        float2 f0 = __half22float2(p0);
        float2 f1 = __half22float2(p1);
        acc[0] += f0.x; acc[1] += f0.y; acc[2] += f1.x; acc[3] += f1.y;
    }
    if (j + 1 < deg) {
        int s0 = bk[j], s1 = bk[j + 1];
        j += 2;
        int2 v0 = ((const int2*)(g_h2h + s0 * 8))[lane];
        int2 v1 = ((const int2*)(g_h2h + s1 * 8))[lane];
        float2 f0 = __half22float2(__hadd2(as_h2(v0.x), as_h2(v1.x)));
        float2 f1 = __half22float2(__hadd2(as_h2(v0.y), as_h2(v1.y)));
        acc[0] += f0.x; acc[1] += f0.y; acc[2] += f1.x; acc[3] += f1.y;
    }
    if (j < deg) {
        int2 v = ((const int2*)(g_h2h + bk[j] * 8))[lane];
        float2 f0 = __half22float2(as_h2(v.x));
        float2 f1 = __half22float2(as_h2(v.y));
        acc[0] += f0.x; acc[1] += f0.y; acc[2] += f1.x; acc[3] += f1.y;
    }
    float sc = g_dinv[d];
    float4 b = ((const float4*)b2)[lane];
    float y0 = fmaf(acc[0], sc, b.x);
    float y1 = fmaf(acc[1], sc, b.y);
    float y2 = fmaf(acc[2], sc, b.z);
    float y3 = fmaf(acc[3], sc, b.w);
    float m = fmaxf(fmaxf(y0, y1), fmaxf(y2, y3));
    m = fmaxf(m, __shfl_xor_sync(0xffffffffu, m, 1, 4));
    m = fmaxf(m, __shfl_xor_sync(0xffffffffu, m, 2, 4));
    float s = expf(y0 - m) + expf(y1 - m) + expf(y2 - m) + expf(y3 - m);
    s += __shfl_xor_sync(0xffffffffu, s, 1, 4);
    s += __shfl_xor_sync(0xffffffffu, s, 2, 4);
    float lse = m + logf(s);
    float4 o = make_float4(y0 - lse, y1 - lse, y2 - lse, y3 - lse);
    ((float4*)&out[d * 16])[lane] = o;
}

extern "C" void kernel_launch(void* const* d_in, const int* in_sizes, int n_in,
                              void* d_out, int out_size) {
    const float* x  = (const float*)d_in[0];
    const int*   ei = (const int*)d_in[1];     // int32 [2, E]
    const float* W1 = (const float*)d_in[2];
    const float* b1 = (const float*)d_in[3];
    const float* W2 = (const float*)d_in[4];
    const float* b2 = (const float*)d_in[5];
    float*       out = (float*)d_out;

    const int TB = 256;

    k_zero  <<<(N_NODES / 4 + TB - 1) / TB, TB>>>();
    k_build <<<(N_EDGES / 4 + TB - 1) / TB, TB>>>(ei);
    k_gemm1 <<<(N_NODES + 127) / 128, TB>>>(x, W1);
    k_agg1  <<<(N_NODES + 31) / 32, TB>>>(b1);
    k_gemm2 <<<(N_NODES + 63) / 64, dim3(16, 16)>>>(W2);
    k_agg2  <<<(N_NODES + 63) / 64, TB>>>(b2, out);
}